// round 5
// baseline (speedup 1.0000x reference)
#include <cuda_runtime.h>
#include <cuda_bf16.h>

#define TT 2048
#define CC 64
#define EE 16
#define WARPS_PER_BLOCK 4
#define NTHREADS (32 * WARPS_PER_BLOCK)
#define TB WARPS_PER_BLOCK          // one t-row per warp
#define EPSF 1e-6f
// logf(1e-6f) - log1pf(-1e-6f)
#define LOGIT_EPS (-13.815510f)

#define RED2(v) v += __shfl_xor_sync(0xffffffffu, v, 16);

__global__ __launch_bounds__(NTHREADS, 8)
void role_learner_kernel(const float* __restrict__ pbar,
                         const float* __restrict__ rho_dir,
                         const float* __restrict__ rho_ind,
                         const float* __restrict__ gamma_dir,
                         const float* __restrict__ gamma_ind,
                         const float* __restrict__ gamma_ctr,
                         const float* __restrict__ bias,
                         float* __restrict__ out)
{
    const int tid  = threadIdx.x;
    const int lane = tid & 31;
    const int e    = lane & (EE - 1);      // lane bits [3:0] = expert
    const int part = lane >> 4;            // lane bit  [4]   = c-half
    const int w    = tid >> 5;
    const int t    = blockIdx.x * TB + w;  // one t-row per warp

    // part 0 -> c in [0,32), part 1 -> c in [32,64): contiguous halves so all
    // loop loads are base + immediate offset after full unroll.
    const float* prow = pbar    + t * CC + part * (CC / 2);
    const float* rdp  = rho_dir + (part * (CC / 2)) * EE + e;
    const float* rip  = rho_ind + (part * (CC / 2)) * EE + e;

    // broadcast per-e params early (overlap with loop)
    const float gd = __ldg(gamma_dir + e);
    const float gi = __ldg(gamma_ind + e);
    const float gc = __ldg(gamma_ctr + e);
    const float bs = __ldg(bias + e);

    // moments S_k = sum_c a^k (k=1..8) over this half's 32 c's, plus the
    // product of direct terms (single log at the end).
    float S1 = 0.f, S2 = 0.f, S3 = 0.f, S4 = 0.f;
    float S5 = 0.f, S6 = 0.f, S7 = 0.f, S8 = 0.f;
    float prod = 1.0f;

    #pragma unroll
    for (int j = 0; j < CC / 2; j++) {
        const float p  = __ldg(prow + j);                    // warp-broadcast
        const float rd = __saturatef(__ldg(rdp + j * EE));   // 64B coalesced
        const float ri = __saturatef(__ldg(rip + j * EE));

        prod *= fmaxf(fmaf(-p, rd, 1.0f), EPSF);

        const float a  = p * ri;
        const float a2 = a  * a;
        const float a3 = a2 * a;
        const float a4 = a2 * a2;
        S1 += a;  S2 += a2;  S3 += a3;  S4 += a4;
        S5 = fmaf(a4, a,  S5);
        S6 = fmaf(a4, a2, S6);
        S7 = fmaf(a4, a3, S7);
        S8 = fmaf(a4, a4, S8);
    }

    float LD = __logf(prod);   // partial sum_c log(max(1 - p*rd, eps))

    // single butterfly round: partner differs in lane bit 4
    RED2(LD);
    RED2(S1); RED2(S2); RED2(S3); RED2(S4);
    RED2(S5); RED2(S6); RED2(S7); RED2(S8);

    // Z = sum_{i<j} log(1 - a_i a_j) = -0.5 * sum_{k=1..4} (S_k^2 - S_{2k})/k
    const float Z = -0.5f * ( (S1*S1 - S2)
                    + 0.5f          * (S2*S2 - S4)
                    + 0.3333333433f * (S3*S3 - S6)
                    + 0.25f         * (S4*S4 - S8) );

    const float eD = __expf(LD);   // 1 - D (exact complement)
    const float eI = __expf(Z);    // 1 - I
    const float D  = 1.0f - eD;
    const float I  = 1.0f - eI;
    const float ctr    = eD * eI;                 // (1-D)(1-I)
    const float om_ctr = fmaf(-eD, eI, 1.0f);     // 1 - ctr
    const float lctr   = LD + Z;                  // exact log(ctr)

    // logits with reference clipping; log(1-x) taken from the exact log-sums
    float lD;
    if (D < EPSF)       lD = LOGIT_EPS;
    else if (eD < EPSF) lD = -LOGIT_EPS;
    else                lD = __logf(D) - LD;

    float lI;
    if (I < EPSF)       lI = LOGIT_EPS;
    else if (eI < EPSF) lI = -LOGIT_EPS;
    else                lI = __logf(I) - Z;

    float lC;
    if (ctr < EPSF)         lC = LOGIT_EPS;
    else if (om_ctr < EPSF) lC = -LOGIT_EPS;
    else                    lC = lctr - __logf(om_ctr);

    const float logits = gd * lD + gi * lI + gc * lC + bs;

    if (part == 0)
        out[t * EE + e] = 1.0f / (1.0f + __expf(-logits));
}

extern "C" void kernel_launch(void* const* d_in, const int* in_sizes, int n_in,
                              void* d_out, int out_size)
{
    (void)in_sizes; (void)n_in; (void)out_size;
    const float* pbar      = (const float*)d_in[0];
    const float* rho_dir   = (const float*)d_in[1];
    const float* rho_ind   = (const float*)d_in[2];
    // d_in[3] = rho_ctr (unused in forward)
    const float* gamma_dir = (const float*)d_in[4];
    const float* gamma_ind = (const float*)d_in[5];
    const float* gamma_ctr = (const float*)d_in[6];
    const float* bias      = (const float*)d_in[7];
    float* out = (float*)d_out;

    role_learner_kernel<<<TT / TB, NTHREADS>>>(
        pbar, rho_dir, rho_ind, gamma_dir, gamma_ind, gamma_ctr, bias, out);
}

// round 6
// speedup vs baseline: 1.1480x; 1.1480x over previous
#include <cuda_runtime.h>
#include <cuda_bf16.h>

#define TT 2048
#define CC 64
#define EE 16
#define WARPS_PER_BLOCK 4
#define NTHREADS (32 * WARPS_PER_BLOCK)   // 128
#define TB WARPS_PER_BLOCK                // one t-row per warp
#define EPSF 1e-6f
// logf(1e-6f) - log1pf(-1e-6f)
#define LOGIT_EPS (-13.815510f)

#define RED2(v) v += __shfl_xor_sync(0xffffffffu, v, 16);

__global__ __launch_bounds__(NTHREADS, 8)
void role_learner_kernel(const float* __restrict__ pbar,
                         const float* __restrict__ rho_dir,
                         const float* __restrict__ rho_ind,
                         const float* __restrict__ gamma_dir,
                         const float* __restrict__ gamma_ind,
                         const float* __restrict__ gamma_ctr,
                         const float* __restrict__ bias,
                         float* __restrict__ out)
{
    __shared__ float sp [TB * CC];   // p tile   [TB][C]
    __shared__ float srd[CC * EE];   // rho_dir  [C][E], clipped
    __shared__ float sri[CC * EE];   // rho_ind  [C][E], clipped

    const int tid = threadIdx.x;
    const int t0  = blockIdx.x * TB;

    // float4 staging. p tile: TB*CC = 256 floats = 64 float4.
    if (tid < (TB * CC) / 4)
        ((float4*)sp)[tid] = ((const float4*)(pbar + t0 * CC))[tid];
    // rho tiles: 1024 floats = 256 float4 each -> 2 per thread per array.
    {
        const float4* s0 = (const float4*)rho_dir;
        const float4* s1 = (const float4*)rho_ind;
        #pragma unroll
        for (int i = tid; i < (CC * EE) / 4; i += NTHREADS) {
            float4 v = s0[i];
            v.x = __saturatef(v.x); v.y = __saturatef(v.y);
            v.z = __saturatef(v.z); v.w = __saturatef(v.w);
            ((float4*)srd)[i] = v;
            float4 w = s1[i];
            w.x = __saturatef(w.x); w.y = __saturatef(w.y);
            w.z = __saturatef(w.z); w.w = __saturatef(w.w);
            ((float4*)sri)[i] = w;
        }
    }
    __syncthreads();

    // lane bits: [3:0]=e, [4]=part. One t-row per warp.
    const int lane = tid & 31;
    const int e    = lane & (EE - 1);
    const int part = lane >> 4;
    const int w    = tid >> 5;
    const float* prow = &sp[w * CC];

    // per-e params (L1-resident broadcasts, overlap with loop)
    const float gd = __ldg(gamma_dir + e);
    const float gi = __ldg(gamma_ind + e);
    const float gc = __ldg(gamma_ctr + e);
    const float bs = __ldg(bias + e);

    // Moments S_k = sum_c a^k for k in {1,2,3,4,6,8} (S5, S7 are not needed:
    // Z uses S1..S4 squared and S_{2k} = S2,S4,S6,S8 only), plus the product
    // of direct terms (single log at the end).
    float S1 = 0.f, S2 = 0.f, S3 = 0.f, S4 = 0.f, S6 = 0.f, S8 = 0.f;
    float prod = 1.0f;

    #pragma unroll
    for (int j = 0; j < CC / 2; j++) {
        const int c  = 2 * j + part;        // interleave -> conflict-free banks
        const float p  = prow[c];           // 2-address broadcast
        const float rd = srd[c * EE + e];   // bank = (16*part + e) % 32
        const float ri = sri[c * EE + e];

        prod *= fmaxf(fmaf(-p, rd, 1.0f), EPSF);

        const float a  = p * ri;
        const float a2 = a  * a;
        const float a3 = a2 * a;
        const float a4 = a2 * a2;
        S1 += a;  S2 += a2;  S3 += a3;  S4 += a4;
        S6 = fmaf(a4, a2, S6);
        S8 = fmaf(a4, a4, S8);
    }

    float LD = __logf(prod);   // partial sum_c log(max(1 - p*rd, eps))

    // single butterfly round: partner differs in lane bit 4
    RED2(LD);
    RED2(S1); RED2(S2); RED2(S3); RED2(S4); RED2(S6); RED2(S8);

    // Z = sum_{i<j} log(1 - a_i a_j) = -0.5 * sum_{k=1..4} (S_k^2 - S_{2k})/k
    const float Z = -0.5f * ( (S1*S1 - S2)
                    + 0.5f          * (S2*S2 - S4)
                    + 0.3333333433f * (S3*S3 - S6)
                    + 0.25f         * (S4*S4 - S8) );

    const float eD = __expf(LD);   // 1 - D (exact complement)
    const float eI = __expf(Z);    // 1 - I
    const float D  = 1.0f - eD;
    const float I  = 1.0f - eI;
    const float ctr    = eD * eI;                 // (1-D)(1-I)
    const float om_ctr = fmaf(-eD, eI, 1.0f);     // 1 - ctr
    const float lctr   = LD + Z;                  // exact log(ctr)

    // logits with reference clipping; log(1-x) from the exact log-sums
    float lD;
    if (D < EPSF)       lD = LOGIT_EPS;
    else if (eD < EPSF) lD = -LOGIT_EPS;
    else                lD = __logf(D) - LD;

    float lI;
    if (I < EPSF)       lI = LOGIT_EPS;
    else if (eI < EPSF) lI = -LOGIT_EPS;
    else                lI = __logf(I) - Z;

    float lC;
    if (ctr < EPSF)         lC = LOGIT_EPS;
    else if (om_ctr < EPSF) lC = -LOGIT_EPS;
    else                    lC = lctr - __logf(om_ctr);

    const float logits = gd * lD + gi * lI + gc * lC + bs;

    if (part == 0)
        out[(t0 + w) * EE + e] = 1.0f / (1.0f + __expf(-logits));
}

extern "C" void kernel_launch(void* const* d_in, const int* in_sizes, int n_in,
                              void* d_out, int out_size)
{
    (void)in_sizes; (void)n_in; (void)out_size;
    const float* pbar      = (const float*)d_in[0];
    const float* rho_dir   = (const float*)d_in[1];
    const float* rho_ind   = (const float*)d_in[2];
    // d_in[3] = rho_ctr (unused in forward)
    const float* gamma_dir = (const float*)d_in[4];
    const float* gamma_ind = (const float*)d_in[5];
    const float* gamma_ctr = (const float*)d_in[6];
    const float* bias      = (const float*)d_in[7];
    float* out = (float*)d_out;

    role_learner_kernel<<<TT / TB, NTHREADS>>>(
        pbar, rho_dir, rho_ind, gamma_dir, gamma_ind, gamma_ctr, bias, out);
}